// round 1
// baseline (speedup 1.0000x reference)
#include <cuda_runtime.h>
#include <math.h>

#define EPS_F 1e-6f
#define NCOL 64
#define LSTEP 63

// Per-launch derived parameters (computed on device by setup_kernel).
__device__ float g_coef[NCOL];        // log-domain dot-product coefficients (geo fast path)
__device__ int   g_all_geo;           // 1 if every step takes the geometric-mean branch
__device__ float g_a[LSTEP];          // a_vec (NaN replacement value)
__device__ float g_r[LSTEP];          // power-mean exponent r
__device__ float g_wacc[LSTEP];
__device__ float g_wnew[LSTEP];
__device__ int   g_geo[LSTEP];        // per-step geo flag (generic path)

__global__ void vln_setup_kernel(const float* __restrict__ a_raw,
                                 const float* __restrict__ w_raw) {
    if (blockIdx.x != 0 || threadIdx.x != 0) return;

    float wmin = w_raw[0], wmax = w_raw[0];
    for (int i = 1; i < LSTEP; i++) {
        float w = w_raw[i];
        wmin = fminf(wmin, w);
        wmax = fmaxf(wmax, w);
    }
    float denom = fmaxf(wmax - wmin, 1e-8f);

    int all_geo = 1;
    for (int i = 0; i < LSTEP; i++) {
        float a   = 3.0f / (1.0f + expf(-a_raw[i])) - 1.0f;
        float a_c = fminf(fmaxf(a, EPS_F), 1.0f - EPS_F);
        float r   = (1.0f - 2.0f * a_c) / (a_c * (1.0f - a_c));
        int geo   = fabsf(r) < 0.001f;
        float wn  = fminf(fmaxf((w_raw[i] - wmin) / denom, 0.0f), 1.0f);
        g_a[i]    = a;
        g_r[i]    = r;
        g_wnew[i] = wn;
        g_wacc[i] = 1.0f - wn;
        g_geo[i]  = geo;
        all_geo &= geo;
    }
    g_all_geo = all_geo;

    // Fold the 63-step geometric-mean scan into per-column coefficients:
    //   c_k = wnew[k-1] * P[k]  (k >= 2),  c0 = wacc[0]*P[1], c1 = wnew[0]*P[1]
    //   P[j] = prod_{i=j}^{62} wacc[i],  P[63] = 1
    float P = 1.0f;
    for (int k = LSTEP; k >= 2; k--) {      // k = 63 .. 2
        g_coef[k] = g_wnew[k - 1] * P;
        P *= g_wacc[k - 1];                 // P becomes P[k-1]
    }
    g_coef[0] = g_wacc[0] * P;              // P == P[1] here
    g_coef[1] = g_wnew[0] * P;
}

__device__ __forceinline__ float clip01(float v) {
    return fminf(fmaxf(v, EPS_F), 1.0f);
}

// Generic single aggregation step (slow path)
__device__ float aggregate_step(float acc, float right, int i) {
    float acc_c = clip01(acc);
    float rc    = clip01(right);
    if (g_geo[i]) {
        return powf(acc_c, g_wacc[i]) * powf(rc, g_wnew[i]);
    }
    float r  = g_r[i];
    float pm = powf(g_wacc[i] * powf(acc_c, r) + g_wnew[i] * powf(rc, r), 1.0f / r);
    return pm;
}

__global__ void __launch_bounds__(256)
vln_main_kernel(const float* __restrict__ x, float* __restrict__ out, int B) {
    __shared__ float sc[NCOL];
    __shared__ int   s_geo;
    int tid = threadIdx.x;
    if (tid < NCOL) sc[tid] = g_coef[tid];
    if (tid == 0)   s_geo   = g_all_geo;
    __syncthreads();

    int row = blockIdx.x * blockDim.x + tid;
    if (row >= B) return;

    if (s_geo) {
        // Fast path: out = exp2( sum_k c_k * log2(clip(x_k)) )
        const float4* xr = reinterpret_cast<const float4*>(x) + (size_t)row * (NCOL / 4);
        float s0 = 0.0f, s1 = 0.0f, s2 = 0.0f, s3 = 0.0f;
#pragma unroll
        for (int j = 0; j < NCOL / 4; j++) {
            float4 v = __ldg(xr + j);
            s0 = fmaf(sc[4 * j + 0], __log2f(clip01(v.x)), s0);
            s1 = fmaf(sc[4 * j + 1], __log2f(clip01(v.y)), s1);
            s2 = fmaf(sc[4 * j + 2], __log2f(clip01(v.z)), s2);
            s3 = fmaf(sc[4 * j + 3], __log2f(clip01(v.w)), s3);
        }
        out[row] = exp2f((s0 + s1) + (s2 + s3));
    } else {
        // Generic sequential path (matches reference scan semantics)
        const float* xr = x + (size_t)row * NCOL;
        float acc = aggregate_step(xr[0], xr[1], 0);
        for (int i = 1; i < LSTEP; i++) {
            float z = aggregate_step(acc, xr[i + 1], i);
            if (isnan(z)) z = g_a[i];
            acc = z;
        }
        out[row] = acc;
    }
}

extern "C" void kernel_launch(void* const* d_in, const int* in_sizes, int n_in,
                              void* d_out, int out_size) {
    const float* x     = (const float*)d_in[0];
    const float* a_raw = (const float*)d_in[1];
    const float* w_raw = (const float*)d_in[2];
    float* out = (float*)d_out;

    int B = in_sizes[0] / NCOL;

    vln_setup_kernel<<<1, 1>>>(a_raw, w_raw);

    int threads = 256;
    int blocks  = (B + threads - 1) / threads;
    vln_main_kernel<<<blocks, threads>>>(x, out, B);
}

// round 2
// speedup vs baseline: 1.6512x; 1.6512x over previous
#include <cuda_runtime.h>
#include <math.h>

#define EPS_F 1e-6f
#define NCOL 64
#define LSTEP 63

// Per-launch derived parameters (computed on device by setup_kernel).
__device__ __align__(16) float g_coef[NCOL];  // log-domain coefficients (geo fast path)
__device__ int   g_all_geo;                   // 1 if every step is the geometric branch
__device__ float g_a[LSTEP];                  // a_vec (NaN replacement value)
__device__ float g_r[LSTEP];                  // power-mean exponent r
__device__ float g_wacc[LSTEP];
__device__ float g_wnew[LSTEP];
__device__ int   g_geo[LSTEP];                // per-step geo flag (generic path)

// 64-thread parallel setup: per-step math in parallel; tiny serial parts on t0.
__global__ void vln_setup_kernel(const float* __restrict__ a_raw,
                                 const float* __restrict__ w_raw) {
    __shared__ float sw[LSTEP];
    __shared__ float s_denom, s_wmin;
    int t = threadIdx.x;

    if (t < LSTEP) sw[t] = w_raw[t];
    __syncthreads();

    if (t == 0) {
        float wmin = sw[0], wmax = sw[0];
#pragma unroll
        for (int i = 1; i < LSTEP; i++) {
            wmin = fminf(wmin, sw[i]);
            wmax = fmaxf(wmax, sw[i]);
        }
        s_wmin  = wmin;
        s_denom = fmaxf(wmax - wmin, 1e-8f);
    }
    __syncthreads();

    __shared__ int s_geo_all[2];
    if (t < 2) s_geo_all[t] = 1;
    __syncthreads();

    if (t < LSTEP) {
        float a   = 3.0f / (1.0f + expf(-a_raw[t])) - 1.0f;
        float a_c = fminf(fmaxf(a, EPS_F), 1.0f - EPS_F);
        float r   = (1.0f - 2.0f * a_c) / (a_c * (1.0f - a_c));
        int geo   = fabsf(r) < 0.001f;
        float wn  = fminf(fmaxf((sw[t] - s_wmin) / s_denom, 0.0f), 1.0f);
        g_a[t]    = a;
        g_r[t]    = r;
        g_wnew[t] = wn;
        g_wacc[t] = 1.0f - wn;
        g_geo[t]  = geo;
        if (!geo) atomicAnd(&s_geo_all[0], 0);
        // stash into smem for the suffix-product pass
        sw[t] = wn;  // reuse sw for wnew
    }
    __shared__ float swa[LSTEP];
    if (t < LSTEP) swa[t] = 1.0f - sw[t];
    __syncthreads();

    if (t == 0) {
        g_all_geo = s_geo_all[0];
        // Fold the 63-step geometric scan into per-column coefficients:
        //   c_k = wnew[k-1] * P[k] (k>=2), c0 = wacc[0]*P[1], c1 = wnew[0]*P[1]
        //   P[j] = prod_{i=j}^{62} wacc[i]
        float P = 1.0f;
#pragma unroll
        for (int k = LSTEP; k >= 2; k--) {
            g_coef[k] = sw[k - 1] * P;
            P *= swa[k - 1];
        }
        g_coef[0] = swa[0] * P;
        g_coef[1] = sw[0] * P;
    }
}

__device__ __forceinline__ float clip01(float v) {
    return fminf(fmaxf(v, EPS_F), 1.0f);
}

// Generic single aggregation step (slow path, semantics-exact)
__device__ float aggregate_step(float acc, float right, int i) {
    float acc_c = clip01(acc);
    float rc    = clip01(right);
    if (g_geo[i]) {
        return powf(acc_c, g_wacc[i]) * powf(rc, g_wnew[i]);
    }
    float r = g_r[i];
    return powf(g_wacc[i] * powf(acc_c, r) + g_wnew[i] * powf(rc, r), 1.0f / r);
}

// 16 lanes per row: lane s loads float4 at column 4s. A warp covers 2 rows =
// 4 contiguous 128B lines per LDG.128 (fully coalesced), then 4-step shfl
// butterfly reduces the 16 partial log-sums.
__global__ void __launch_bounds__(256)
vln_main_kernel(const float* __restrict__ x, float* __restrict__ out, int B) {
    int gtid = blockIdx.x * blockDim.x + threadIdx.x;
    int row  = gtid >> 4;
    int sub  = gtid & 15;
    if (row >= B) return;

    if (g_all_geo) {
        float4 v = __ldg(reinterpret_cast<const float4*>(x + (size_t)row * NCOL) + sub);
        float4 c = *(reinterpret_cast<const float4*>(g_coef) + sub);

        float s;
        s  = c.x * __log2f(clip01(v.x));
        s  = fmaf(c.y, __log2f(clip01(v.y)), s);
        s  = fmaf(c.z, __log2f(clip01(v.z)), s);
        s  = fmaf(c.w, __log2f(clip01(v.w)), s);

        s += __shfl_xor_sync(0xFFFFFFFFu, s, 8);
        s += __shfl_xor_sync(0xFFFFFFFFu, s, 4);
        s += __shfl_xor_sync(0xFFFFFFFFu, s, 2);
        s += __shfl_xor_sync(0xFFFFFFFFu, s, 1);

        if (sub == 0) out[row] = exp2f(s);
    } else {
        // Generic sequential path: group leader walks the row (unused here).
        if (sub == 0) {
            const float* xr = x + (size_t)row * NCOL;
            float acc = aggregate_step(xr[0], xr[1], 0);
            for (int i = 1; i < LSTEP; i++) {
                float z = aggregate_step(acc, xr[i + 1], i);
                if (isnan(z)) z = g_a[i];
                acc = z;
            }
            out[row] = acc;
        }
    }
}

extern "C" void kernel_launch(void* const* d_in, const int* in_sizes, int n_in,
                              void* d_out, int out_size) {
    const float* x     = (const float*)d_in[0];
    const float* a_raw = (const float*)d_in[1];
    const float* w_raw = (const float*)d_in[2];
    float* out = (float*)d_out;

    int B = in_sizes[0] / NCOL;

    vln_setup_kernel<<<1, 64>>>(a_raw, w_raw);

    long long total_threads = (long long)B * 16;
    int threads = 256;
    int blocks  = (int)((total_threads + threads - 1) / threads);
    vln_main_kernel<<<blocks, threads>>>(x, out, B);
}

// round 3
// speedup vs baseline: 2.2724x; 1.3762x over previous
#include <cuda_runtime.h>
#include <math.h>

#define EPS_F 1e-6f
#define NCOL 64
#define LSTEP 63

// Per-launch derived parameters (computed on device by setup_kernel).
__device__ __align__(16) float g_coef[NCOL];  // log-domain coefficients (geo fast path)
__device__ int   g_all_geo;                   // 1 if every step is the geometric branch
__device__ float g_a[LSTEP];                  // a_vec (NaN replacement value)
__device__ float g_r[LSTEP];                  // power-mean exponent r
__device__ float g_wacc[LSTEP];
__device__ float g_wnew[LSTEP];
__device__ int   g_geo[LSTEP];                // per-step geo flag (generic path)

// 64-thread parallel setup: per-step math in parallel; tiny serial parts on t0.
__global__ void vln_setup_kernel(const float* __restrict__ a_raw,
                                 const float* __restrict__ w_raw) {
    __shared__ float sw[LSTEP];
    __shared__ float swa[LSTEP];
    __shared__ float s_denom, s_wmin;
    __shared__ int s_geo_all;
    int t = threadIdx.x;

    if (t == 0) s_geo_all = 1;
    if (t < LSTEP) sw[t] = w_raw[t];
    __syncthreads();

    if (t == 0) {
        float wmin = sw[0], wmax = sw[0];
#pragma unroll
        for (int i = 1; i < LSTEP; i++) {
            wmin = fminf(wmin, sw[i]);
            wmax = fmaxf(wmax, sw[i]);
        }
        s_wmin  = wmin;
        s_denom = fmaxf(wmax - wmin, 1e-8f);
    }
    __syncthreads();

    if (t < LSTEP) {
        float a   = 3.0f / (1.0f + expf(-a_raw[t])) - 1.0f;
        float a_c = fminf(fmaxf(a, EPS_F), 1.0f - EPS_F);
        float r   = (1.0f - 2.0f * a_c) / (a_c * (1.0f - a_c));
        int geo   = fabsf(r) < 0.001f;
        float wn  = fminf(fmaxf((sw[t] - s_wmin) / s_denom, 0.0f), 1.0f);
        g_a[t]    = a;
        g_r[t]    = r;
        g_wnew[t] = wn;
        g_wacc[t] = 1.0f - wn;
        g_geo[t]  = geo;
        if (!geo) atomicAnd(&s_geo_all, 0);
        sw[t]  = wn;          // reuse: wnew
        swa[t] = 1.0f - wn;   // wacc
    }
    __syncthreads();

    if (t == 0) {
        g_all_geo = s_geo_all;
        // Fold the 63-step geometric scan into per-column coefficients:
        //   c_k = wnew[k-1] * P[k] (k>=2), c0 = wacc[0]*P[1], c1 = wnew[0]*P[1]
        //   P[j] = prod_{i=j}^{62} wacc[i]
        float P = 1.0f;
#pragma unroll
        for (int k = LSTEP; k >= 2; k--) {
            g_coef[k] = sw[k - 1] * P;
            P *= swa[k - 1];
        }
        g_coef[0] = swa[0] * P;
        g_coef[1] = sw[0] * P;
    }
}

__device__ __forceinline__ float clip01(float v) {
    return fminf(fmaxf(v, EPS_F), 1.0f);
}

// Generic single aggregation step (slow path, semantics-exact)
__device__ float aggregate_step(float acc, float right, int i) {
    float acc_c = clip01(acc);
    float rc    = clip01(right);
    if (g_geo[i]) {
        return powf(acc_c, g_wacc[i]) * powf(rc, g_wnew[i]);
    }
    float r = g_r[i];
    return powf(g_wacc[i] * powf(acc_c, r) + g_wnew[i] * powf(rc, r), 1.0f / r);
}

__device__ __forceinline__ float dot8_log(const float4& v0, const float4& v1,
                                          const float4& c0, const float4& c1) {
    float s;
    s = c0.x * __log2f(clip01(v0.x));
    s = fmaf(c0.y, __log2f(clip01(v0.y)), s);
    s = fmaf(c0.z, __log2f(clip01(v0.z)), s);
    s = fmaf(c0.w, __log2f(clip01(v0.w)), s);
    s = fmaf(c1.x, __log2f(clip01(v1.x)), s);
    s = fmaf(c1.y, __log2f(clip01(v1.y)), s);
    s = fmaf(c1.z, __log2f(clip01(v1.z)), s);
    s = fmaf(c1.w, __log2f(clip01(v1.w)), s);
    return s;
}

// 8 lanes per row, 2 rows per thread (rows i and i+B/2).
// Each thread front-batches 4 independent LDG.128s (MLP=4). A warp's first
// LDG covers 4 consecutive rows = 8 full 128B lines. Reduction = two 3-step
// shfl butterflies over the 8-lane group.
__global__ void __launch_bounds__(256)
vln_main_kernel(const float* __restrict__ x, float* __restrict__ out, int B) {
    int gtid = blockIdx.x * blockDim.x + threadIdx.x;
    int half = B >> 1;
    int i    = gtid >> 3;
    int s    = gtid & 7;
    if (i >= half) return;

    if (g_all_geo) {
        int rowA = i;
        int rowB = i + half;

        const float4* pc = reinterpret_cast<const float4*>(g_coef) + 2 * s;
        const float4* pa = reinterpret_cast<const float4*>(x + (size_t)rowA * NCOL) + 2 * s;
        const float4* pb = reinterpret_cast<const float4*>(x + (size_t)rowB * NCOL) + 2 * s;

        // Front-batched independent loads (MLP=4)
        float4 a0 = __ldg(pa);
        float4 a1 = __ldg(pa + 1);
        float4 b0 = __ldg(pb);
        float4 b1 = __ldg(pb + 1);
        float4 c0 = pc[0];
        float4 c1 = pc[1];

        float sa = dot8_log(a0, a1, c0, c1);
        float sb = dot8_log(b0, b1, c0, c1);

        sa += __shfl_xor_sync(0xFFFFFFFFu, sa, 4);
        sb += __shfl_xor_sync(0xFFFFFFFFu, sb, 4);
        sa += __shfl_xor_sync(0xFFFFFFFFu, sa, 2);
        sb += __shfl_xor_sync(0xFFFFFFFFu, sb, 2);
        sa += __shfl_xor_sync(0xFFFFFFFFu, sa, 1);
        sb += __shfl_xor_sync(0xFFFFFFFFu, sb, 1);

        if (s == 0) {
            out[rowA] = exp2f(sa);
            out[rowB] = exp2f(sb);
        }
    } else {
        // Generic sequential path (unused for these inputs): leader walks rows.
        if (s == 0) {
            int rows[2] = {i, i + half};
#pragma unroll
            for (int q = 0; q < 2; q++) {
                const float* xr = x + (size_t)rows[q] * NCOL;
                float acc = aggregate_step(xr[0], xr[1], 0);
                for (int k = 1; k < LSTEP; k++) {
                    float z = aggregate_step(acc, xr[k + 1], k);
                    if (isnan(z)) z = g_a[k];
                    acc = z;
                }
                out[rows[q]] = acc;
            }
        }
    }
}

extern "C" void kernel_launch(void* const* d_in, const int* in_sizes, int n_in,
                              void* d_out, int out_size) {
    const float* x     = (const float*)d_in[0];
    const float* a_raw = (const float*)d_in[1];
    const float* w_raw = (const float*)d_in[2];
    float* out = (float*)d_out;

    int B = in_sizes[0] / NCOL;   // B is even for this problem (524288)

    vln_setup_kernel<<<1, 64>>>(a_raw, w_raw);

    long long total_threads = ((long long)B / 2) * 8;
    int threads = 256;
    int blocks  = (int)((total_threads + threads - 1) / threads);
    vln_main_kernel<<<blocks, threads>>>(x, out, B);
}